// round 1
// baseline (speedup 1.0000x reference)
#include <cuda_runtime.h>
#include <math.h>

#define BB 8
#define NN 1024
#define DM 512
#define NH 8
#define HD 64
#define NS_TOK 1

// Scratch (device globals: no allocations allowed in kernel_launch)
__device__ float g_qkv[(size_t)BB * NN * 3 * DM];   // [b][n][1536] : q|k|v
__device__ float g_attn[(size_t)BB * NN * DM];      // [b][n][512]

// ---------------------------------------------------------------------------
// GEMM: C[m][n] = sum_k A[m][k] * W[n][k] (+ bias[n])   (A row-major, W row-major)
// BM=128, BN=64, BK=16, 256 threads, 8x4 per-thread microtile.
// ---------------------------------------------------------------------------
__global__ __launch_bounds__(256) void gemm_nt(
    const float* __restrict__ A, const float* __restrict__ W,
    const float* __restrict__ bias, float* __restrict__ C,
    int M, int Nc, int K)
{
    __shared__ float As[16][132];
    __shared__ float Bs[16][68];
    const int tid = threadIdx.x;
    const int ty = tid >> 4, tx = tid & 15;
    const int brow = blockIdx.y * 128, bcol = blockIdx.x * 64;

    float acc[8][4];
#pragma unroll
    for (int i2 = 0; i2 < 8; i2++)
#pragma unroll
        for (int j2 = 0; j2 < 4; j2++) acc[i2][j2] = 0.f;

    for (int k0 = 0; k0 < K; k0 += 16) {
#pragma unroll
        for (int t = tid; t < 2048; t += 256) {
            int m2 = t >> 4, k2 = t & 15;
            As[k2][m2] = A[(size_t)(brow + m2) * K + k0 + k2];
        }
#pragma unroll
        for (int t = tid; t < 1024; t += 256) {
            int n2 = t >> 4, k2 = t & 15;
            Bs[k2][n2] = W[(size_t)(bcol + n2) * K + k0 + k2];
        }
        __syncthreads();
#pragma unroll
        for (int kk = 0; kk < 16; kk++) {
            float a[8], bf[4];
#pragma unroll
            for (int i2 = 0; i2 < 8; i2++) a[i2] = As[kk][ty * 8 + i2];
#pragma unroll
            for (int j2 = 0; j2 < 4; j2++) bf[j2] = Bs[kk][tx * 4 + j2];
#pragma unroll
            for (int i2 = 0; i2 < 8; i2++)
#pragma unroll
                for (int j2 = 0; j2 < 4; j2++)
                    acc[i2][j2] = fmaf(a[i2], bf[j2], acc[i2][j2]);
        }
        __syncthreads();
    }

#pragma unroll
    for (int i2 = 0; i2 < 8; i2++) {
        int row = brow + ty * 8 + i2;
        int col = bcol + tx * 4;
        float4 r;
        r.x = acc[i2][0]; r.y = acc[i2][1]; r.z = acc[i2][2]; r.w = acc[i2][3];
        if (bias) {
            r.x += bias[col + 0]; r.y += bias[col + 1];
            r.z += bias[col + 2]; r.w += bias[col + 3];
        }
        *(float4*)(C + (size_t)row * Nc + col) = r;
    }
}

// ---------------------------------------------------------------------------
// Fused relative-position-bias attention.
// Grid: B * (N/32) blocks, 256 threads.
// Thread (i = tid&31, h = tid>>5) owns output row (i0+i) of head h.
// Per j-tile of 32: stage K/V rows (all heads) in SMEM, compute the shared
// pairwise bias MLP cooperatively (gelu hidden layer shared across heads),
// then per-thread dot products + online softmax + AV accumulation.
// SMEM: k 16384 + v 16384 + bias 8192 + misc ~720 floats  = ~167 KB dynamic.
// ---------------------------------------------------------------------------
__global__ __launch_bounds__(256) void attn_bias_kernel(
    const float* __restrict__ qkv, const float* __restrict__ coords,
    const unsigned char* __restrict__ kpm,
    const float* __restrict__ w1, const float* __restrict__ b1,
    const float* __restrict__ w2, const float* __restrict__ b2,
    const float* __restrict__ cscales, const float* __restrict__ alphap,
    float* __restrict__ outp)
{
    extern __shared__ float sm[];
    float* k_s    = sm;              // 32 * 512
    float* v_s    = sm + 16384;      // 32 * 512
    float* bias_s = sm + 32768;      // 32(j) * 8(h) * 32(i)
    float* ci_s   = sm + 40960;      // 32 * 4
    float* cj_s   = sm + 41088;      // 32 * 4
    float* w1_s   = sm + 41216;      // 32 * 4
    float* b1_s   = sm + 41344;      // 32
    float* w2_s   = sm + 41376;      // 8 * 32
    float* b2_s   = sm + 41632;      // 8
    float* mask_s = sm + 41640;      // 32

    const int tid = threadIdx.x;
    const int b   = blockIdx.x >> 5;
    const int i0  = (blockIdx.x & 31) * 32;
    const int i   = tid & 31;
    const int h   = tid >> 5;
    const float alpha = alphap[0];

    if (tid < 128) w1_s[tid] = w1[tid];
    if (tid < 32)  b1_s[tid] = b1[tid];
    w2_s[tid] = (tid < 256) ? w2[tid] : 0.f;  // 256 threads, 256 elems
    if (tid < 8)   b2_s[tid] = b2[tid];
    if (tid < 32) {
        int ig = i0 + tid;
        ci_s[tid * 4 + 0] = coords[((size_t)b * NN + ig) * 3 + 0] / cscales[0];
        ci_s[tid * 4 + 1] = coords[((size_t)b * NN + ig) * 3 + 1] / cscales[1];
        ci_s[tid * 4 + 2] = coords[((size_t)b * NN + ig) * 3 + 2] / cscales[2];
        ci_s[tid * 4 + 3] = 0.f;
    }

    // Load this thread's q vector (row i0+i, head h) into registers.
    float q[64];
    {
        const float4* qp =
            (const float4*)(qkv + ((size_t)(b * NN + i0 + i)) * 1536 + h * 64);
#pragma unroll
        for (int t = 0; t < 16; t++) {
            float4 f = qp[t];
            q[4*t+0] = f.x; q[4*t+1] = f.y; q[4*t+2] = f.z; q[4*t+3] = f.w;
        }
    }

    float acc[64];
#pragma unroll
    for (int d = 0; d < 64; d++) acc[d] = 0.f;
    float mrun = -INFINITY, l = 0.f;

    __syncthreads();

    for (int j0 = 0; j0 < NN; j0 += 32) {
        // ---- stage K/V tile (rows j0..j0+31, all heads) ----
#pragma unroll
        for (int t = tid; t < 4096; t += 256) {
            int jj = t >> 7, c4 = t & 127;
            const float4* src =
                (const float4*)(qkv + ((size_t)(b * NN + j0 + jj)) * 1536);
            ((float4*)k_s)[jj * 128 + c4] = src[128 + c4];  // k block
            ((float4*)v_s)[jj * 128 + c4] = src[256 + c4];  // v block
        }
        if (tid < 32) {
            int jg = j0 + tid;
            mask_s[tid] = kpm[(size_t)b * NN + jg] ? 1.f : 0.f;
            cj_s[tid * 4 + 0] = coords[((size_t)b * NN + jg) * 3 + 0] / cscales[0];
            cj_s[tid * 4 + 1] = coords[((size_t)b * NN + jg) * 3 + 1] / cscales[1];
            cj_s[tid * 4 + 2] = coords[((size_t)b * NN + jg) * 3 + 2] / cscales[2];
            cj_s[tid * 4 + 3] = 0.f;
        }
        __syncthreads();

        // ---- Phase A: pairwise bias MLP (shared across heads), 4 pairs/thread ----
#pragma unroll 1
        for (int pp = 0; pp < 4; pp++) {
            int p  = tid + 256 * pp;
            int jj = p >> 5, ii = p & 31;
            float dx = ci_s[ii * 4 + 0] - cj_s[jj * 4 + 0];
            float dy = ci_s[ii * 4 + 1] - cj_s[jj * 4 + 1];
            float dz = ci_s[ii * 4 + 2] - cj_s[jj * 4 + 2];
            float dist = sqrtf(dx * dx + dy * dy + dz * dz);
            float bo[8];
#pragma unroll
            for (int hh = 0; hh < 8; hh++) bo[hh] = b2_s[hh];
#pragma unroll 4
            for (int kk = 0; kk < 32; kk++) {
                float t2 = b1_s[kk];
                t2 = fmaf(w1_s[kk * 4 + 0], dx,   t2);
                t2 = fmaf(w1_s[kk * 4 + 1], dy,   t2);
                t2 = fmaf(w1_s[kk * 4 + 2], dz,   t2);
                t2 = fmaf(w1_s[kk * 4 + 3], dist, t2);
                // exact gelu (approximate=False): x * 0.5 * (1 + erf(x/sqrt(2)))
                float g = 0.5f * t2 * (1.f + erff(t2 * 0.70710678118654752f));
#pragma unroll
                for (int hh = 0; hh < 8; hh++)
                    bo[hh] = fmaf(g, w2_s[hh * 32 + kk], bo[hh]);
            }
            float zf = ((i0 + ii) >= NS_TOK && (j0 + jj) >= NS_TOK) ? 1.f : 0.f;
#pragma unroll
            for (int hh = 0; hh < 8; hh++)
                bias_s[jj * 256 + hh * 32 + ii] = bo[hh] * zf;
        }
        __syncthreads();

        // ---- Phase B: logits (written back into bias_s slots), online softmax, AV ----
        float tmax = -INFINITY;
        for (int jj = 0; jj < 32; jj++) {
            const float4* kp = (const float4*)(k_s + jj * 512 + h * 64);
            float d0 = 0.f, d1 = 0.f, d2 = 0.f, d3 = 0.f;
#pragma unroll
            for (int t = 0; t < 16; t++) {
                float4 f = kp[t];
                d0 = fmaf(q[4*t+0], f.x, d0);
                d1 = fmaf(q[4*t+1], f.y, d1);
                d2 = fmaf(q[4*t+2], f.z, d2);
                d3 = fmaf(q[4*t+3], f.w, d3);
            }
            float lgv = (d0 + d1 + d2 + d3) * 0.125f
                        + alpha * bias_s[jj * 256 + h * 32 + i];
            if (mask_s[jj] > 0.5f) lgv = -1e30f;
            bias_s[jj * 256 + h * 32 + i] = lgv;   // own slot: no race
            tmax = fmaxf(tmax, lgv);
        }
        float mnew = fmaxf(mrun, tmax);
        float corr = __expf(mrun - mnew);   // first tile: exp(-inf)=0
        mrun = mnew;
        l *= corr;
#pragma unroll
        for (int d = 0; d < 64; d++) acc[d] *= corr;

        for (int jj = 0; jj < 32; jj++) {
            float p = __expf(bias_s[jj * 256 + h * 32 + i] - mrun);
            l += p;
            const float4* vp = (const float4*)(v_s + jj * 512 + h * 64);
#pragma unroll
            for (int t = 0; t < 16; t++) {
                float4 f = vp[t];
                acc[4*t+0] = fmaf(p, f.x, acc[4*t+0]);
                acc[4*t+1] = fmaf(p, f.y, acc[4*t+1]);
                acc[4*t+2] = fmaf(p, f.z, acc[4*t+2]);
                acc[4*t+3] = fmaf(p, f.w, acc[4*t+3]);
            }
        }
        __syncthreads();
    }

    float invl = 1.f / l;
    float* op = outp + ((size_t)(b * NN + i0 + i)) * 512 + h * 64;
#pragma unroll
    for (int t = 0; t < 16; t++) {
        float4 f;
        f.x = acc[4*t+0] * invl; f.y = acc[4*t+1] * invl;
        f.z = acc[4*t+2] * invl; f.w = acc[4*t+3] * invl;
        ((float4*)op)[t] = f;
    }
}

// ---------------------------------------------------------------------------
extern "C" void kernel_launch(void* const* d_in, const int* in_sizes, int n_in,
                              void* d_out, int out_size)
{
    const float* x      = (const float*)d_in[0];
    const float* coords = (const float*)d_in[1];
    const unsigned char* kpm = (const unsigned char*)d_in[2];
    const float* qkv_w  = (const float*)d_in[3];
    const float* out_w  = (const float*)d_in[4];
    const float* out_b  = (const float*)d_in[5];
    const float* alpha  = (const float*)d_in[6];
    const float* w1     = (const float*)d_in[7];
    const float* b1     = (const float*)d_in[8];
    const float* w2     = (const float*)d_in[9];
    const float* b2     = (const float*)d_in[10];
    const float* cs     = (const float*)d_in[11];
    float* out = (float*)d_out;

    float* qkvp = nullptr;
    float* attnp = nullptr;
    cudaGetSymbolAddress((void**)&qkvp, g_qkv);
    cudaGetSymbolAddress((void**)&attnp, g_attn);

    const int SMEM = 41672 * 4;  // ~167 KB
    cudaFuncSetAttribute(attn_bias_kernel,
                         cudaFuncAttributeMaxDynamicSharedMemorySize, SMEM);

    // 1) QKV projection: [8192,512] @ [512,1536]
    dim3 g1(1536 / 64, 8192 / 128);
    gemm_nt<<<g1, 256>>>(x, qkv_w, nullptr, qkvp, BB * NN, 3 * DM, DM);

    // 2) Fused bias + attention
    attn_bias_kernel<<<BB * (NN / 32), 256, SMEM>>>(
        qkvp, coords, kpm, w1, b1, w2, b2, cs, alpha, attnp);

    // 3) Output projection: [8192,512] @ [512,512] + bias
    dim3 g3(512 / 64, 8192 / 128);
    gemm_nt<<<g3, 256>>>(attnp, out_w, out_b, out, BB * NN, DM, DM);
}